// round 3
// baseline (speedup 1.0000x reference)
#include <cuda_runtime.h>
#include <cuda_bf16.h>
#include <cstdint>

// Problem constants
#define B_    32
#define U_    4096
#define D_    512
#define H_    4
#define HD_   128
#define CK_   31
#define CF_   32
#define AU_   512

// Fused kernel tiling
#define UC    128            // u rows per CTA
#define NC    (U_ / UC)      // 32 chunks per batch
#define ST    16             // rows per pipeline stage
#define NSUB  (UC / ST)      // 8
#define NSTAGE 3
#define TILE_BYTES (ST * D_ * 4)   // 32768

// ---------------- scratch (device globals) ----------------------------------
__device__ float g_KEFF[CK_ * H_];
__device__ float g_V[B_ * H_ * D_];
__device__ float g_P[(size_t)B_ * H_ * U_];                 // exp(energy), unnormalized
__device__ float g_CTXP[(size_t)B_ * NC * H_ * D_];         // per-chunk ctx partials
__device__ float g_SP[B_ * NC * H_];                        // per-chunk sum of p
__device__ float g_CTX[B_ * H_ * D_];                       // normalized context
__device__ float g_S[B_ * H_];                              // global sums
__device__ float g_OUTP[4 * B_ * AU_];                      // out GEMM partials

// ---------------- PTX helpers -----------------------------------------------
__device__ __forceinline__ uint32_t smem_u32(const void* p) {
    uint32_t a;
    asm("{ .reg .u64 t; cvta.to.shared.u64 t, %1; cvt.u32.u64 %0, t; }"
        : "=r"(a) : "l"(p));
    return a;
}
__device__ __forceinline__ void mbar_init(uint32_t mbar, uint32_t cnt) {
    asm volatile("mbarrier.init.shared.b64 [%0], %1;" :: "r"(mbar), "r"(cnt) : "memory");
}
__device__ __forceinline__ void mbar_expect_tx(uint32_t mbar, uint32_t bytes) {
    asm volatile("mbarrier.arrive.expect_tx.shared.b64 _, [%0], %1;"
                 :: "r"(mbar), "r"(bytes) : "memory");
}
__device__ __forceinline__ void mbar_wait(uint32_t mbar, uint32_t parity) {
    uint32_t done;
    asm volatile(
        "{\n\t.reg .pred p;\n\t"
        "mbarrier.try_wait.parity.acquire.cta.shared::cta.b64 p, [%1], %2;\n\t"
        "selp.b32 %0, 1, 0, p;\n\t}"
        : "=r"(done) : "r"(mbar), "r"(parity) : "memory");
    if (!done) {
        asm volatile(
            "{\n\t.reg .pred P1;\n\t"
            "W_%=:\n\t"
            "mbarrier.try_wait.parity.acquire.cta.shared::cta.b64 P1, [%0], %1, 0x989680;\n\t"
            "@P1 bra.uni D_%=;\n\t"
            "bra.uni W_%=;\n\t"
            "D_%=:\n\t}"
            :: "r"(mbar), "r"(parity) : "memory");
    }
}
__device__ __forceinline__ void bulk_g2s(uint32_t dst, const void* src,
                                         uint32_t bytes, uint32_t mbar) {
    asm volatile(
        "cp.async.bulk.shared::cta.global.mbarrier::complete_tx::bytes "
        "[%0], [%1], %2, [%3];"
        :: "r"(dst), "l"(src), "r"(bytes), "r"(mbar) : "memory");
}
__device__ __forceinline__ void fence_proxy_async_sc() {
    asm volatile("fence.proxy.async.shared::cta;" ::: "memory");
}
// packed fp32 pair FMA: d = a*b + d (elementwise on 2 lanes)
__device__ __forceinline__ void fma2(unsigned long long& d,
                                     unsigned long long a,
                                     unsigned long long b) {
    asm("fma.rn.f32x2 %0, %1, %2, %0;" : "+l"(d) : "l"(a), "l"(b));
}
__device__ __forceinline__ unsigned long long pack2(float lo, float hi) {
    unsigned long long r;
    asm("mov.b64 %0, {%1, %2};" : "=l"(r) : "f"(lo), "f"(hi));
    return r;
}
__device__ __forceinline__ float2 unpack2(unsigned long long v) {
    float2 r;
    asm("mov.b64 {%0, %1}, %2;" : "=f"(r.x), "=f"(r.y) : "l"(v));
    return r;
}

// ---------------- kernel: effective conv kernel -----------------------------
__global__ void keff_kernel(const float* __restrict__ ck,
                            const float* __restrict__ Wloc)
{
    int i = threadIdx.x;
    if (i < CK_ * H_) {
        int k = i >> 2, h = i & 3;
        float s = 0.f;
        #pragma unroll
        for (int f = 0; f < CF_; f++) s += ck[k * CF_ + f] * Wloc[f * H_ + h];
        g_KEFF[i] = s;
    }
}

// ---------------- kernel: phi & v -------------------------------------------
__global__ void phiv_kernel(const float* __restrict__ dec,
                            const float* __restrict__ Wphi,
                            const float* __restrict__ bphi,
                            const float* __restrict__ Wpsi)
{
    int bh = blockIdx.x;
    int b = bh >> 2, h = bh & 3;
    __shared__ float dec_sm[D_];
    __shared__ float phi_sm[HD_];
    int tid = threadIdx.x;   // 128

    for (int i = tid; i < D_; i += 128) dec_sm[i] = dec[(size_t)b * D_ + i];
    __syncthreads();

    float acc = bphi[h * HD_ + tid];
    const float* w = Wphi + (size_t)h * D_ * HD_ + tid;
    #pragma unroll 8
    for (int d = 0; d < D_; d++) acc += dec_sm[d] * w[(size_t)d * HD_];
    phi_sm[tid] = acc;
    __syncthreads();

    for (int e = tid; e < D_; e += 128) {
        const float4* wp = reinterpret_cast<const float4*>(
            Wpsi + ((size_t)h * D_ + e) * HD_);
        float vv = 0.f;
        #pragma unroll 8
        for (int k4 = 0; k4 < HD_ / 4; k4++) {
            float4 ww = wp[k4];
            vv += ww.x * phi_sm[4 * k4 + 0] + ww.y * phi_sm[4 * k4 + 1]
                + ww.z * phi_sm[4 * k4 + 2] + ww.w * phi_sm[4 * k4 + 3];
        }
        g_V[(size_t)bh * D_ + e] = vv;
    }
}

// ---------------- fused: energy + exp + context partials --------------------
// grid (NC, B), block 256, 2 CTAs/SM target.
// smem float layout (102 KB total):
//   [0)      enc stages : 3 * ST*D = 24576
//   [24576)  pall       : H*UC    = 512   (p values, head-major)
//   [25088)  p2         : ST*H*2  = 128   (p duplicated pairs, u64 per (r,h))
//   [25216)  prevs      : UC+30   = 158
//   [25374)  keffs      : 124
//   [25500)  mbar       : 3 u64   = 6
#define SMEM_FUSED_FLOATS 25508
#define SMEM_FUSED_BYTES (SMEM_FUSED_FLOATS * 4)

__global__ void __launch_bounds__(256, 2)
fused_kernel(const float* __restrict__ enc,
             const float* __restrict__ prev)
{
    extern __shared__ float smem[];
    float* pall  = smem + NSTAGE * ST * D_;           // 24576
    unsigned long long* p2 =
        reinterpret_cast<unsigned long long*>(smem + 25088);  // [r*H + h]
    float* prevs = smem + 25216;
    float* keffs = smem + 25374;
    uint32_t barb = smem_u32(smem + 25500);

    int tid  = threadIdx.x;
    int warp = tid >> 5, lane = tid & 31;
    int b  = blockIdx.y;
    int u0 = blockIdx.x * UC;
    const float* enc_base = enc + ((size_t)b * U_ + u0) * D_;

    if (tid == 0) {
        mbar_init(barb + 0, 1);
        mbar_init(barb + 8, 1);
        mbar_init(barb + 16, 1);
        fence_proxy_async_sc();
    }
    __syncthreads();

    if (tid == 0) {
        #pragma unroll
        for (int s = 0; s < NSTAGE; s++) {
            mbar_expect_tx(barb + 8 * s, TILE_BYTES);
            bulk_g2s(smem_u32(smem + s * ST * D_),
                     enc_base + s * ST * D_, TILE_BYTES, barb + 8 * s);
        }
    }

    // stage prev halo + keff while copies fly
    for (int i = tid; i < UC + 30; i += 256) {
        int gu = u0 + i - 15;
        prevs[i] = (gu >= 0 && gu < U_) ? prev[(size_t)b * U_ + gu] : 0.f;
    }
    if (tid < CK_ * H_) keffs[tid] = g_KEFF[tid];

    // v in registers as packed pairs: lane covers float4 slots lane+32*i
    ulonglong2 vr2[H_][4];
    #pragma unroll
    for (int h = 0; h < H_; h++) {
        const ulonglong2* vp = reinterpret_cast<const ulonglong2*>(
            g_V + (size_t)(b * H_ + h) * D_);
        #pragma unroll
        for (int i = 0; i < 4; i++) vr2[h][i] = vp[lane + 32 * i];
    }

    unsigned long long ctx2[H_];   // packed (col 2tid, 2tid+1)
    #pragma unroll
    for (int h = 0; h < H_; h++) ctx2[h] = 0ull;

    __syncthreads();  // prevs/keffs ready

    for (int s = 0; s < NSUB; s++) {
        int slot = s % NSTAGE;
        mbar_wait(barb + 8 * slot, (s / NSTAGE) & 1);
        const float* tile = smem + slot * ST * D_;

        // ---- energy + exp: warp handles rows 2*warp, 2*warp+1 ----
        #pragma unroll
        for (int rr = 0; rr < 2; rr++) {
            int r = warp * 2 + rr;
            const ulonglong2* row = reinterpret_cast<const ulonglong2*>(tile + r * D_);
            unsigned long long a2[H_] = {0ull, 0ull, 0ull, 0ull};
            #pragma unroll
            for (int i = 0; i < 4; i++) {
                ulonglong2 x = row[lane + 32 * i];
                #pragma unroll
                for (int h = 0; h < H_; h++) {
                    fma2(a2[h], x.x, vr2[h][i].x);
                    fma2(a2[h], x.y, vr2[h][i].y);
                }
            }
            float a[H_];
            #pragma unroll
            for (int h = 0; h < H_; h++) {
                float2 f = unpack2(a2[h]);
                a[h] = f.x + f.y;
            }
            #pragma unroll
            for (int off = 16; off; off >>= 1) {
                #pragma unroll
                for (int h = 0; h < H_; h++)
                    a[h] += __shfl_xor_sync(0xffffffffu, a[h], off);
            }
            if (lane < H_) {
                float e = (lane == 0) ? a[0] : (lane == 1) ? a[1]
                        : (lane == 2) ? a[2] : a[3];
                int uu = s * ST + r;
                float lb = 0.f;
                #pragma unroll
                for (int k = 0; k < CK_; k++)
                    lb += prevs[uu + k] * keffs[k * H_ + lane];
                float p = __expf(e + lb);
                pall[lane * UC + uu] = p;
                p2[r * H_ + lane] = pack2(p, p);
            }
        }
        __syncthreads();

        // ---- context accumulation (thread owns cols 2tid, 2tid+1) ----
        {
            const unsigned long long* tp =
                reinterpret_cast<const unsigned long long*>(tile) + tid;
            #pragma unroll 4
            for (int r = 0; r < ST; r++) {
                const ulonglong2* q =
                    reinterpret_cast<const ulonglong2*>(p2 + r * H_);
                ulonglong2 q01 = q[0], q23 = q[1];
                unsigned long long x = tp[r * (D_ / 2)];
                fma2(ctx2[0], x, q01.x);
                fma2(ctx2[1], x, q01.y);
                fma2(ctx2[2], x, q23.x);
                fma2(ctx2[3], x, q23.y);
            }
        }
        __syncthreads();

        // ---- prefetch subtile s+NSTAGE into freed slot ----
        if (tid == 0 && s + NSTAGE < NSUB) {
            mbar_expect_tx(barb + 8 * slot, TILE_BYTES);
            bulk_g2s(smem_u32(smem + slot * ST * D_),
                     enc_base + (s + NSTAGE) * ST * D_, TILE_BYTES, barb + 8 * slot);
        }
    }

    // ---- per-chunk sum of p (warp h reduces pall[h][0..127]) ----
    size_t chunk = (size_t)b * NC + blockIdx.x;
    if (warp < H_) {
        const float* ph = pall + warp * UC;
        float sp = ph[lane] + ph[lane + 32] + ph[lane + 64] + ph[lane + 96];
        #pragma unroll
        for (int off = 16; off; off >>= 1)
            sp += __shfl_xor_sync(0xffffffffu, sp, off);
        if (lane == 0) g_SP[chunk * H_ + warp] = sp;
    }

    // ---- write ctx partials + raw p ----
    #pragma unroll
    for (int h = 0; h < H_; h++) {
        float2 f = unpack2(ctx2[h]);
        float* cp = g_CTXP + (chunk * H_ + h) * D_ + 2 * tid;
        cp[0] = f.x; cp[1] = f.y;
    }
    #pragma unroll
    for (int j = 0; j < 2; j++) {
        int idx = tid + 256 * j;          // [0,512)
        int h = idx >> 7, uu = idx & 127;
        g_P[((size_t)(b * H_ + h)) * U_ + u0 + uu] = pall[h * UC + uu];
    }
}

// ---------------- combine partials per (b,h) --------------------------------
// grid (2, H, B), block 256; each thread one column
__global__ void combine_kernel()
{
    int half = blockIdx.x, h = blockIdx.y, b = blockIdx.z;
    int tid = threadIdx.x;
    int col = half * 256 + tid;
    __shared__ float S_sm;

    if (tid < 32) {
        float sc = g_SP[((size_t)b * NC + tid) * H_ + h];
        #pragma unroll
        for (int off = 16; off; off >>= 1)
            sc += __shfl_xor_sync(0xffffffffu, sc, off);
        if (tid == 0) {
            S_sm = sc;
            if (half == 0) g_S[b * H_ + h] = sc;
        }
    }
    __syncthreads();
    float invS = 1.f / S_sm;

    float a = 0.f;
    #pragma unroll 8
    for (int c = 0; c < NC; c++)
        a += g_CTXP[(((size_t)b * NC + c) * H_ + h) * D_ + col];
    g_CTX[(size_t)(b * H_ + h) * D_ + col] = a * invS;
}

// ---------------- attention weights (mean over heads) -----------------------
// grid (4, B), block 256; writes d_out offset B*AU
__global__ void aw_kernel(float* __restrict__ out)
{
    int z = blockIdx.x, b = blockIdx.y;
    float i0 = 0.25f / g_S[b * H_ + 0];
    float i1 = 0.25f / g_S[b * H_ + 1];
    float i2 = 0.25f / g_S[b * H_ + 2];
    float i3 = 0.25f / g_S[b * H_ + 3];
    const float* p0 = g_P + (size_t)(b * H_ + 0) * U_ + z * 1024;
    const float* p1 = g_P + (size_t)(b * H_ + 1) * U_ + z * 1024;
    const float* p2 = g_P + (size_t)(b * H_ + 2) * U_ + z * 1024;
    const float* p3 = g_P + (size_t)(b * H_ + 3) * U_ + z * 1024;
    float* o = out + (size_t)B_ * AU_ + (size_t)b * U_ + z * 1024;
    for (int u = threadIdx.x; u < 1024; u += 256)
        o[u] = p0[u] * i0 + p1[u] * i1 + p2[u] * i2 + p3[u] * i3;
}

// ---------------- out GEMM partials ------------------------------------------
// grid (16 colgroups, 4 i-slices), block 256 = 32 cols x 8 bgroups (4 b each)
// dynamic smem: c_sm[32][512] = 64KB
__global__ void outp_kernel(const float* __restrict__ Wout)
{
    extern __shared__ float c_sm[];   // [b][i] : 32 x 512
    int cg = blockIdx.x, s = blockIdx.y;
    int tid = threadIdx.x;
    int col = cg * 32 + (tid & 31);
    int bg  = tid >> 5;               // 0..7 -> b in {4*bg .. 4*bg+3}

    // load ctx slice: c_sm[b][i] = g_CTX[b*2048 + s*512 + i]
    for (int k = tid; k < 32 * 512; k += 256) {
        int bb = k >> 9, i = k & 511;
        c_sm[k] = g_CTX[(size_t)bb * (H_ * D_) + s * 512 + i];
    }
    __syncthreads();

    float acc0 = 0.f, acc1 = 0.f, acc2 = 0.f, acc3 = 0.f;
    const float* wp = Wout + (size_t)s * 512 * AU_ + col;
    const float* c0 = c_sm + (4 * bg + 0) * 512;
    const float* c1 = c_sm + (4 * bg + 1) * 512;
    const float* c2 = c_sm + (4 * bg + 2) * 512;
    const float* c3 = c_sm + (4 * bg + 3) * 512;
    #pragma unroll 8
    for (int i = 0; i < 512; i++) {
        float w = wp[(size_t)i * AU_];
        acc0 += c0[i] * w;
        acc1 += c1[i] * w;
        acc2 += c2[i] * w;
        acc3 += c3[i] * w;
    }
    float* op = g_OUTP + (size_t)s * B_ * AU_ + col;
    op[(4 * bg + 0) * AU_] = acc0;
    op[(4 * bg + 1) * AU_] = acc1;
    op[(4 * bg + 2) * AU_] = acc2;
    op[(4 * bg + 3) * AU_] = acc3;
}

// ---------------- out final: grid B, block 512 ------------------------------
__global__ void outf_kernel(const float* __restrict__ bout,
                            float* __restrict__ out)
{
    int b = blockIdx.x, t = threadIdx.x;
    float v = bout[t]
            + g_OUTP[(0 * B_ + b) * AU_ + t] + g_OUTP[(1 * B_ + b) * AU_ + t]
            + g_OUTP[(2 * B_ + b) * AU_ + t] + g_OUTP[(3 * B_ + b) * AU_ + t];
    out[(size_t)b * AU_ + t] = v;
}

// ---------------------------------------------------------------------------
extern "C" void kernel_launch(void* const* d_in, const int* in_sizes, int n_in,
                              void* d_out, int out_size)
{
    const float* dec   = (const float*)d_in[0];
    const float* enc   = (const float*)d_in[1];
    const float* prev  = (const float*)d_in[2];
    const float* Wphi  = (const float*)d_in[3];
    const float* bphi  = (const float*)d_in[4];
    const float* Wpsi  = (const float*)d_in[5];
    // d_in[6] = bpsi: constant along u per (b,h) -> softmax-invariant, unused
    const float* ck    = (const float*)d_in[7];
    const float* Wloc  = (const float*)d_in[8];
    const float* Wout  = (const float*)d_in[9];
    const float* bout  = (const float*)d_in[10];
    float* out = (float*)d_out;

    cudaFuncSetAttribute(fused_kernel,
                         cudaFuncAttributeMaxDynamicSharedMemorySize,
                         SMEM_FUSED_BYTES);
    cudaFuncSetAttribute(outp_kernel,
                         cudaFuncAttributeMaxDynamicSharedMemorySize,
                         32 * 512 * 4);

    keff_kernel<<<1, 128>>>(ck, Wloc);
    phiv_kernel<<<B_ * H_, 128>>>(dec, Wphi, bphi, Wpsi);
    fused_kernel<<<dim3(NC, B_), 256, SMEM_FUSED_BYTES>>>(enc, prev);
    combine_kernel<<<dim3(2, H_, B_), 256>>>();
    aw_kernel<<<dim3(4, B_), 256>>>(out);
    outp_kernel<<<dim3(16, 4), 256, 32 * 512 * 4>>>(Wout);
    outf_kernel<<<B_, 512>>>(bout, out);
}

// round 4
// speedup vs baseline: 1.1073x; 1.1073x over previous
#include <cuda_runtime.h>
#include <cuda_bf16.h>
#include <cstdint>

// Problem constants
#define B_    32
#define U_    4096
#define D_    512
#define H_    4
#define HD_   128
#define CK_   31
#define CF_   32
#define AU_   512

// Fused kernel tiling
#define UC    128            // u rows per CTA chunk
#define NC    (U_ / UC)      // 32 chunks per batch
#define ST    16             // rows per pipeline stage
#define NSUB  (UC / ST)      // 8
#define TILE_BYTES (ST * D_ * 4)   // 32768

// ---------------- scratch (device globals) ----------------------------------
__device__ float g_KEFF[CK_ * H_];
__device__ float g_V[B_ * H_ * D_];
__device__ float g_P[(size_t)B_ * U_ * H_];                 // exp(energy), [b][u][h]
__device__ float g_CTXP[(size_t)B_ * NC * H_ * D_];         // per-chunk ctx partials
__device__ float g_SP[B_ * NC * H_];                        // per-chunk sum of p
__device__ float g_CTX[B_ * H_ * D_];                       // normalized context
__device__ float g_S[B_ * H_];                              // global sums
__device__ float g_OUTP[4 * B_ * AU_];                      // out GEMM partials

// ---------------- PTX helpers -----------------------------------------------
__device__ __forceinline__ uint32_t smem_u32(const void* p) {
    uint32_t a;
    asm("{ .reg .u64 t; cvta.to.shared.u64 t, %1; cvt.u32.u64 %0, t; }"
        : "=r"(a) : "l"(p));
    return a;
}
__device__ __forceinline__ void mbar_init(uint32_t mbar, uint32_t cnt) {
    asm volatile("mbarrier.init.shared.b64 [%0], %1;" :: "r"(mbar), "r"(cnt) : "memory");
}
__device__ __forceinline__ void mbar_expect_tx(uint32_t mbar, uint32_t bytes) {
    asm volatile("mbarrier.arrive.expect_tx.shared.b64 _, [%0], %1;"
                 :: "r"(mbar), "r"(bytes) : "memory");
}
__device__ __forceinline__ void mbar_wait(uint32_t mbar, uint32_t parity) {
    uint32_t done;
    asm volatile(
        "{\n\t.reg .pred p;\n\t"
        "mbarrier.try_wait.parity.acquire.cta.shared::cta.b64 p, [%1], %2;\n\t"
        "selp.b32 %0, 1, 0, p;\n\t}"
        : "=r"(done) : "r"(mbar), "r"(parity) : "memory");
    if (!done) {
        asm volatile(
            "{\n\t.reg .pred P1;\n\t"
            "W_%=:\n\t"
            "mbarrier.try_wait.parity.acquire.cta.shared::cta.b64 P1, [%0], %1, 0x989680;\n\t"
            "@P1 bra.uni D_%=;\n\t"
            "bra.uni W_%=;\n\t"
            "D_%=:\n\t}"
            :: "r"(mbar), "r"(parity) : "memory");
    }
}
__device__ __forceinline__ void bulk_g2s(uint32_t dst, const void* src,
                                         uint32_t bytes, uint32_t mbar) {
    asm volatile(
        "cp.async.bulk.shared::cta.global.mbarrier::complete_tx::bytes "
        "[%0], [%1], %2, [%3];"
        :: "r"(dst), "l"(src), "r"(bytes), "r"(mbar) : "memory");
}
__device__ __forceinline__ void fence_proxy_async_sc() {
    asm volatile("fence.proxy.async.shared::cta;" ::: "memory");
}
__device__ __forceinline__ void fma2(unsigned long long& d,
                                     unsigned long long a,
                                     unsigned long long b) {
    asm("fma.rn.f32x2 %0, %1, %2, %0;" : "+l"(d) : "l"(a), "l"(b));
}
__device__ __forceinline__ unsigned long long pack2(float lo, float hi) {
    unsigned long long r;
    asm("mov.b64 %0, {%1, %2};" : "=l"(r) : "f"(lo), "f"(hi));
    return r;
}
__device__ __forceinline__ float2 unpack2(unsigned long long v) {
    float2 r;
    asm("mov.b64 {%0, %1}, %2;" : "=f"(r.x), "=f"(r.y) : "l"(v));
    return r;
}

// ---------------- kernel: effective conv kernel -----------------------------
__global__ void keff_kernel(const float* __restrict__ ck,
                            const float* __restrict__ Wloc)
{
    int i = threadIdx.x;
    if (i < CK_ * H_) {
        int k = i >> 2, h = i & 3;
        float s = 0.f;
        #pragma unroll
        for (int f = 0; f < CF_; f++) s += ck[k * CF_ + f] * Wloc[f * H_ + h];
        g_KEFF[i] = s;
    }
}

// ---------------- kernel: phi & v -------------------------------------------
// grid B*H, block 256. Phase 1: 2 d-slices x 128 k. Phase 2: v.
__global__ void phiv_kernel(const float* __restrict__ dec,
                            const float* __restrict__ Wphi,
                            const float* __restrict__ bphi,
                            const float* __restrict__ Wpsi)
{
    int bh = blockIdx.x;
    int b = bh >> 2, h = bh & 3;
    __shared__ float dec_sm[D_];
    __shared__ float phi_part[2][HD_];
    __shared__ float phi_sm[HD_];
    int tid = threadIdx.x;   // 256

    for (int i = tid; i < D_; i += 256) dec_sm[i] = dec[(size_t)b * D_ + i];
    __syncthreads();

    {
        int k = tid & 127, sl = tid >> 7;    // slice 0/1
        const float* w = Wphi + (size_t)h * D_ * HD_ + (size_t)sl * 256 * HD_ + k;
        const float* ds = dec_sm + sl * 256;
        float a0 = 0.f, a1 = 0.f, a2 = 0.f, a3 = 0.f;
        #pragma unroll 8
        for (int d = 0; d < 256; d += 4) {
            a0 += ds[d + 0] * w[(size_t)(d + 0) * HD_];
            a1 += ds[d + 1] * w[(size_t)(d + 1) * HD_];
            a2 += ds[d + 2] * w[(size_t)(d + 2) * HD_];
            a3 += ds[d + 3] * w[(size_t)(d + 3) * HD_];
        }
        phi_part[sl][k] = (a0 + a1) + (a2 + a3);
    }
    __syncthreads();
    if (tid < HD_)
        phi_sm[tid] = phi_part[0][tid] + phi_part[1][tid] + bphi[h * HD_ + tid];
    __syncthreads();

    for (int e = tid; e < D_; e += 256) {
        const float4* wp = reinterpret_cast<const float4*>(
            Wpsi + ((size_t)h * D_ + e) * HD_);
        float vv = 0.f;
        #pragma unroll 8
        for (int k4 = 0; k4 < HD_ / 4; k4++) {
            float4 ww = wp[k4];
            vv += ww.x * phi_sm[4 * k4 + 0] + ww.y * phi_sm[4 * k4 + 1]
                + ww.z * phi_sm[4 * k4 + 2] + ww.w * phi_sm[4 * k4 + 3];
        }
        g_V[(size_t)bh * D_ + e] = vv;
    }
}

// ---------------- fused: energy + exp + context partials --------------------
// grid (NC, B), block 256, 3 CTAs/SM.
// smem float layout (~71 KB):
//   [0)      tiles   : 2 * ST*D = 16384
//   [16384)  pall    : UC*H     = 512    ([uu][h])
//   [16896)  p2      : ST*H*2   = 128    (u64 (p,p) per (r,h))
//   [17024)  lb_sm   : UC*H     = 512    (loc bias, [uu][h])
//   [17536)  prevs   : UC+30    = 158
//   [17694)  keffs   : 124
//   [17818)  mbar    : 2 u64    = 4  (pad to 8B align: starts at 17818*4=71272 -> align)
#define SMEM_FUSED_FLOATS 17828
#define SMEM_FUSED_BYTES (SMEM_FUSED_FLOATS * 4)

__global__ void __launch_bounds__(256, 3)
fused_kernel(const float* __restrict__ enc,
             const float* __restrict__ prev)
{
    extern __shared__ float smem[];
    float* pall  = smem + 2 * ST * D_;                 // 16384
    unsigned long long* p2 =
        reinterpret_cast<unsigned long long*>(smem + 16896);
    float* lb_sm = smem + 17024;
    float* prevs = smem + 17536;
    float* keffs = smem + 17694;
    uint32_t barb = (smem_u32(smem + 17818) + 7) & ~7u;

    int tid  = threadIdx.x;
    int warp = tid >> 5, lane = tid & 31;
    int b  = blockIdx.y;
    int u0 = blockIdx.x * UC;
    const float* enc_base = enc + ((size_t)b * U_ + u0) * D_;

    if (tid == 0) {
        mbar_init(barb + 0, 1);
        mbar_init(barb + 8, 1);
        fence_proxy_async_sc();
    }
    __syncthreads();

    if (tid == 0) {
        mbar_expect_tx(barb + 0, TILE_BYTES);
        bulk_g2s(smem_u32(smem), enc_base, TILE_BYTES, barb + 0);
        mbar_expect_tx(barb + 8, TILE_BYTES);
        bulk_g2s(smem_u32(smem + ST * D_), enc_base + ST * D_, TILE_BYTES, barb + 8);
    }

    // stage prev halo + keff while copies fly
    for (int i = tid; i < UC + 30; i += 256) {
        int gu = u0 + i - 15;
        prevs[i] = (gu >= 0 && gu < U_) ? prev[(size_t)b * U_ + gu] : 0.f;
    }
    if (tid < CK_ * H_) keffs[tid] = g_KEFF[tid];
    __syncthreads();

    // precompute location bias for all (uu, h) of this chunk
    #pragma unroll
    for (int j = 0; j < 2; j++) {
        int idx = tid + 256 * j;          // [0,512)
        int uu = idx >> 2, h = idx & 3;
        float lb = 0.f;
        #pragma unroll
        for (int k = 0; k < CK_; k++)
            lb += prevs[uu + k] * keffs[k * H_ + h];
        lb_sm[idx] = lb;
    }

    // warp-pair head split: warp = pair*2 + j; heads {2j, 2j+1}
    int pairid = warp >> 1, j = warp & 1;
    ulonglong2 vr[2][4];
    #pragma unroll
    for (int g = 0; g < 2; g++) {
        const ulonglong2* vp = reinterpret_cast<const ulonglong2*>(
            g_V + (size_t)(b * H_ + 2 * j + g) * D_);
        #pragma unroll
        for (int i = 0; i < 4; i++) vr[g][i] = vp[lane + 32 * i];
    }

    unsigned long long ctx2[H_] = {0ull, 0ull, 0ull, 0ull};   // cols 2tid,2tid+1

    __syncthreads();  // lb_sm ready

    for (int s = 0; s < NSUB; s++) {
        int slot = s & 1;
        mbar_wait(barb + 8 * slot, (s >> 1) & 1);
        const float* tile = smem + slot * ST * D_;

        // ---- energy + exp: warp handles rows pairid + 4t ----
        #pragma unroll
        for (int t = 0; t < 4; t++) {
            int r = pairid + 4 * t;
            const ulonglong2* row =
                reinterpret_cast<const ulonglong2*>(tile + r * D_);
            unsigned long long a2h[2] = {0ull, 0ull};
            #pragma unroll
            for (int i = 0; i < 4; i++) {
                ulonglong2 x = row[lane + 32 * i];
                fma2(a2h[0], x.x, vr[0][i].x);
                fma2(a2h[0], x.y, vr[0][i].y);
                fma2(a2h[1], x.x, vr[1][i].x);
                fma2(a2h[1], x.y, vr[1][i].y);
            }
            float2 f0 = unpack2(a2h[0]), f1 = unpack2(a2h[1]);
            float a0 = f0.x + f0.y, a1 = f1.x + f1.y;
            #pragma unroll
            for (int off = 16; off; off >>= 1) {
                a0 += __shfl_xor_sync(0xffffffffu, a0, off);
                a1 += __shfl_xor_sync(0xffffffffu, a1, off);
            }
            if (lane == 0) {
                int uu = s * ST + r;
                float2 lb = *reinterpret_cast<const float2*>(
                    lb_sm + uu * H_ + 2 * j);
                float p0 = __expf(a0 + lb.x);
                float p1 = __expf(a1 + lb.y);
                *reinterpret_cast<float2*>(pall + uu * H_ + 2 * j) =
                    make_float2(p0, p1);
                ulonglong2 pp;
                pp.x = pack2(p0, p0);
                pp.y = pack2(p1, p1);
                *reinterpret_cast<ulonglong2*>(p2 + r * H_ + 2 * j) = pp;
            }
        }
        __syncthreads();

        // ---- context accumulation (thread owns cols 2tid, 2tid+1) ----
        {
            const unsigned long long* tp =
                reinterpret_cast<const unsigned long long*>(tile) + tid;
            #pragma unroll 4
            for (int r = 0; r < ST; r++) {
                const ulonglong2* q =
                    reinterpret_cast<const ulonglong2*>(p2 + r * H_);
                ulonglong2 q01 = q[0], q23 = q[1];
                unsigned long long x = tp[r * (D_ / 2)];
                fma2(ctx2[0], x, q01.x);
                fma2(ctx2[1], x, q01.y);
                fma2(ctx2[2], x, q23.x);
                fma2(ctx2[3], x, q23.y);
            }
        }
        __syncthreads();

        // ---- prefetch subtile s+2 into freed slot ----
        if (tid == 0 && s + 2 < NSUB) {
            mbar_expect_tx(barb + 8 * slot, TILE_BYTES);
            bulk_g2s(smem_u32(smem + slot * ST * D_),
                     enc_base + (s + 2) * ST * D_, TILE_BYTES, barb + 8 * slot);
        }
    }

    // ---- per-chunk sum of p (warp h reduces pall[:][h]) ----
    size_t chunk = (size_t)b * NC + blockIdx.x;
    if (warp < H_) {
        float sp = pall[lane * H_ + warp] + pall[(lane + 32) * H_ + warp]
                 + pall[(lane + 64) * H_ + warp] + pall[(lane + 96) * H_ + warp];
        #pragma unroll
        for (int off = 16; off; off >>= 1)
            sp += __shfl_xor_sync(0xffffffffu, sp, off);
        if (lane == 0) g_SP[chunk * H_ + warp] = sp;
    }

    // ---- write ctx partials + raw p ([b][u][h] layout) ----
    #pragma unroll
    for (int h = 0; h < H_; h++) {
        float2 f = unpack2(ctx2[h]);
        *reinterpret_cast<float2*>(
            g_CTXP + (chunk * H_ + h) * D_ + 2 * tid) = f;
    }
    #pragma unroll
    for (int jj = 0; jj < 2; jj++) {
        int idx = tid + 256 * jj;  // [0,512) == [uu][h]
        g_P[((size_t)b * U_ + u0) * H_ + idx] = pall[idx];
    }
}

// ---------------- combine partials per (b,h) --------------------------------
// grid (H, B), block 128; thread owns 4 cols
__global__ void combine_kernel()
{
    int h = blockIdx.x, b = blockIdx.y;
    int tid = threadIdx.x;
    __shared__ float S_sm;

    if (tid < 32) {
        float sc = g_SP[((size_t)b * NC + tid) * H_ + h];
        #pragma unroll
        for (int off = 16; off; off >>= 1)
            sc += __shfl_xor_sync(0xffffffffu, sc, off);
        if (tid == 0) {
            S_sm = sc;
            g_S[b * H_ + h] = sc;
        }
    }
    __syncthreads();
    float invS = 1.f / S_sm;

    float4 a = make_float4(0.f, 0.f, 0.f, 0.f);
    #pragma unroll 4
    for (int c = 0; c < NC; c++) {
        float4 v = *reinterpret_cast<const float4*>(
            g_CTXP + (((size_t)b * NC + c) * H_ + h) * D_ + 4 * tid);
        a.x += v.x; a.y += v.y; a.z += v.z; a.w += v.w;
    }
    a.x *= invS; a.y *= invS; a.z *= invS; a.w *= invS;
    *reinterpret_cast<float4*>(g_CTX + (size_t)(b * H_ + h) * D_ + 4 * tid) = a;
}

// ---------------- attention weights (mean over heads) -----------------------
// grid (4, B), block 256; g_P is [b][u][h]
__global__ void aw_kernel(float* __restrict__ out)
{
    int z = blockIdx.x, b = blockIdx.y;
    float i0 = 0.25f / g_S[b * H_ + 0];
    float i1 = 0.25f / g_S[b * H_ + 1];
    float i2 = 0.25f / g_S[b * H_ + 2];
    float i3 = 0.25f / g_S[b * H_ + 3];
    const float4* p = reinterpret_cast<const float4*>(
        g_P + ((size_t)b * U_ + z * 1024) * H_);
    float* o = out + (size_t)B_ * AU_ + (size_t)b * U_ + z * 1024;
    for (int u = threadIdx.x; u < 1024; u += 256) {
        float4 v = p[u];
        o[u] = v.x * i0 + v.y * i1 + v.z * i2 + v.w * i3;
    }
}

// ---------------- out GEMM partials ------------------------------------------
// grid (16 colgroups, 4 i-slices), block 256 = 32 cols x 8 bgroups (4 b each)
__global__ void outp_kernel(const float* __restrict__ Wout)
{
    extern __shared__ float c_sm[];   // [b][i] : 32 x 512
    int cg = blockIdx.x, s = blockIdx.y;
    int tid = threadIdx.x;
    int col = cg * 32 + (tid & 31);
    int bg  = tid >> 5;

    for (int k = tid; k < 32 * 512; k += 256) {
        int bb = k >> 9, i = k & 511;
        c_sm[k] = g_CTX[(size_t)bb * (H_ * D_) + s * 512 + i];
    }
    __syncthreads();

    float acc0 = 0.f, acc1 = 0.f, acc2 = 0.f, acc3 = 0.f;
    const float* wp = Wout + (size_t)s * 512 * AU_ + col;
    const float* c0 = c_sm + (4 * bg + 0) * 512;
    const float* c1 = c_sm + (4 * bg + 1) * 512;
    const float* c2 = c_sm + (4 * bg + 2) * 512;
    const float* c3 = c_sm + (4 * bg + 3) * 512;
    #pragma unroll 8
    for (int i = 0; i < 512; i++) {
        float w = wp[(size_t)i * AU_];
        acc0 += c0[i] * w;
        acc1 += c1[i] * w;
        acc2 += c2[i] * w;
        acc3 += c3[i] * w;
    }
    float* op = g_OUTP + (size_t)s * B_ * AU_ + col;
    op[(4 * bg + 0) * AU_] = acc0;
    op[(4 * bg + 1) * AU_] = acc1;
    op[(4 * bg + 2) * AU_] = acc2;
    op[(4 * bg + 3) * AU_] = acc3;
}

// ---------------- out final: grid B, block 512 ------------------------------
__global__ void outf_kernel(const float* __restrict__ bout,
                            float* __restrict__ out)
{
    int b = blockIdx.x, t = threadIdx.x;
    float v = bout[t]
            + g_OUTP[(0 * B_ + b) * AU_ + t] + g_OUTP[(1 * B_ + b) * AU_ + t]
            + g_OUTP[(2 * B_ + b) * AU_ + t] + g_OUTP[(3 * B_ + b) * AU_ + t];
    out[(size_t)b * AU_ + t] = v;
}

// ---------------------------------------------------------------------------
extern "C" void kernel_launch(void* const* d_in, const int* in_sizes, int n_in,
                              void* d_out, int out_size)
{
    const float* dec   = (const float*)d_in[0];
    const float* enc   = (const float*)d_in[1];
    const float* prev  = (const float*)d_in[2];
    const float* Wphi  = (const float*)d_in[3];
    const float* bphi  = (const float*)d_in[4];
    const float* Wpsi  = (const float*)d_in[5];
    // d_in[6] = bpsi: constant along u per (b,h) -> softmax-invariant, unused
    const float* ck    = (const float*)d_in[7];
    const float* Wloc  = (const float*)d_in[8];
    const float* Wout  = (const float*)d_in[9];
    const float* bout  = (const float*)d_in[10];
    float* out = (float*)d_out;

    cudaFuncSetAttribute(fused_kernel,
                         cudaFuncAttributeMaxDynamicSharedMemorySize,
                         SMEM_FUSED_BYTES);
    cudaFuncSetAttribute(outp_kernel,
                         cudaFuncAttributeMaxDynamicSharedMemorySize,
                         32 * 512 * 4);

    keff_kernel<<<1, 128>>>(ck, Wloc);
    phiv_kernel<<<B_ * H_, 256>>>(dec, Wphi, bphi, Wpsi);
    fused_kernel<<<dim3(NC, B_), 256, SMEM_FUSED_BYTES>>>(enc, prev);
    combine_kernel<<<dim3(H_, B_), 128>>>();
    aw_kernel<<<dim3(4, B_), 256>>>(out);
    outp_kernel<<<dim3(16, 4), 256, 32 * 512 * 4>>>(Wout);
    outf_kernel<<<B_, 512>>>(bout, out);
}

// round 5
// speedup vs baseline: 1.1129x; 1.0050x over previous
#include <cuda_runtime.h>
#include <cuda_bf16.h>
#include <cstdint>

// Problem constants
#define B_    32
#define U_    4096
#define D_    512
#define H_    4
#define HD_   128
#define CK_   31
#define CF_   32
#define AU_   512

// Fused kernel tiling
#define UC    128            // u rows per CTA chunk
#define NC    (U_ / UC)      // 32 chunks per batch
#define ST    16             // rows per pipeline stage
#define NSUB  (UC / ST)      // 8
#define NSTAGE 3
#define TILE_BYTES (ST * D_ * 4)   // 32768

// ---------------- scratch (device globals) ----------------------------------
__device__ float g_KEFF[CK_ * H_];
__device__ float g_V[B_ * H_ * D_];
__device__ float g_P[(size_t)B_ * U_ * H_];                 // exp(energy), [b][u][h]
__device__ float g_CTXP[(size_t)B_ * NC * H_ * D_];         // per-chunk ctx partials
__device__ float g_SP[B_ * NC * H_];                        // per-chunk sum of p
__device__ float g_CTX[B_ * H_ * D_];                       // normalized context
__device__ float g_S[B_ * H_];                              // global sums
__device__ float g_OUTP[4 * B_ * AU_];                      // out GEMM partials

// ---------------- PTX helpers -----------------------------------------------
__device__ __forceinline__ uint32_t smem_u32(const void* p) {
    uint32_t a;
    asm("{ .reg .u64 t; cvta.to.shared.u64 t, %1; cvt.u32.u64 %0, t; }"
        : "=r"(a) : "l"(p));
    return a;
}
__device__ __forceinline__ void mbar_init(uint32_t mbar, uint32_t cnt) {
    asm volatile("mbarrier.init.shared.b64 [%0], %1;" :: "r"(mbar), "r"(cnt) : "memory");
}
__device__ __forceinline__ void mbar_expect_tx(uint32_t mbar, uint32_t bytes) {
    asm volatile("mbarrier.arrive.expect_tx.shared.b64 _, [%0], %1;"
                 :: "r"(mbar), "r"(bytes) : "memory");
}
__device__ __forceinline__ void mbar_wait(uint32_t mbar, uint32_t parity) {
    uint32_t done;
    asm volatile(
        "{\n\t.reg .pred p;\n\t"
        "mbarrier.try_wait.parity.acquire.cta.shared::cta.b64 p, [%1], %2;\n\t"
        "selp.b32 %0, 1, 0, p;\n\t}"
        : "=r"(done) : "r"(mbar), "r"(parity) : "memory");
    if (!done) {
        asm volatile(
            "{\n\t.reg .pred P1;\n\t"
            "W_%=:\n\t"
            "mbarrier.try_wait.parity.acquire.cta.shared::cta.b64 P1, [%0], %1, 0x989680;\n\t"
            "@P1 bra.uni D_%=;\n\t"
            "bra.uni W_%=;\n\t"
            "D_%=:\n\t}"
            :: "r"(mbar), "r"(parity) : "memory");
    }
}
__device__ __forceinline__ void bulk_g2s(uint32_t dst, const void* src,
                                         uint32_t bytes, uint32_t mbar) {
    asm volatile(
        "cp.async.bulk.shared::cta.global.mbarrier::complete_tx::bytes "
        "[%0], [%1], %2, [%3];"
        :: "r"(dst), "l"(src), "r"(bytes), "r"(mbar) : "memory");
}
__device__ __forceinline__ void fence_proxy_async_sc() {
    asm volatile("fence.proxy.async.shared::cta;" ::: "memory");
}
__device__ __forceinline__ void fma2(unsigned long long& d,
                                     unsigned long long a,
                                     unsigned long long b) {
    asm("fma.rn.f32x2 %0, %1, %2, %0;" : "+l"(d) : "l"(a), "l"(b));
}
__device__ __forceinline__ unsigned long long pack2(float lo, float hi) {
    unsigned long long r;
    asm("mov.b64 %0, {%1, %2};" : "=l"(r) : "f"(lo), "f"(hi));
    return r;
}
__device__ __forceinline__ float2 unpack2(unsigned long long v) {
    float2 r;
    asm("mov.b64 {%0, %1}, %2;" : "=f"(r.x), "=f"(r.y) : "l"(v));
    return r;
}

// ---------------- kernel: effective conv kernel -----------------------------
__global__ void keff_kernel(const float* __restrict__ ck,
                            const float* __restrict__ Wloc)
{
    int i = threadIdx.x;
    if (i < CK_ * H_) {
        int k = i >> 2, h = i & 3;
        float s = 0.f;
        #pragma unroll
        for (int f = 0; f < CF_; f++) s += ck[k * CF_ + f] * Wloc[f * H_ + h];
        g_KEFF[i] = s;
    }
}

// ---------------- kernel: phi & v -------------------------------------------
__global__ void phiv_kernel(const float* __restrict__ dec,
                            const float* __restrict__ Wphi,
                            const float* __restrict__ bphi,
                            const float* __restrict__ Wpsi)
{
    int bh = blockIdx.x;
    int b = bh >> 2, h = bh & 3;
    __shared__ float dec_sm[D_];
    __shared__ float phi_part[2][HD_];
    __shared__ float phi_sm[HD_];
    int tid = threadIdx.x;   // 256

    for (int i = tid; i < D_; i += 256) dec_sm[i] = dec[(size_t)b * D_ + i];
    __syncthreads();

    {
        int k = tid & 127, sl = tid >> 7;
        const float* w = Wphi + (size_t)h * D_ * HD_ + (size_t)sl * 256 * HD_ + k;
        const float* ds = dec_sm + sl * 256;
        float a0 = 0.f, a1 = 0.f, a2 = 0.f, a3 = 0.f;
        #pragma unroll 8
        for (int d = 0; d < 256; d += 4) {
            a0 += ds[d + 0] * w[(size_t)(d + 0) * HD_];
            a1 += ds[d + 1] * w[(size_t)(d + 1) * HD_];
            a2 += ds[d + 2] * w[(size_t)(d + 2) * HD_];
            a3 += ds[d + 3] * w[(size_t)(d + 3) * HD_];
        }
        phi_part[sl][k] = (a0 + a1) + (a2 + a3);
    }
    __syncthreads();
    if (tid < HD_)
        phi_sm[tid] = phi_part[0][tid] + phi_part[1][tid] + bphi[h * HD_ + tid];
    __syncthreads();

    for (int e = tid; e < D_; e += 256) {
        const float4* wp = reinterpret_cast<const float4*>(
            Wpsi + ((size_t)h * D_ + e) * HD_);
        float vv = 0.f;
        #pragma unroll 8
        for (int k4 = 0; k4 < HD_ / 4; k4++) {
            float4 ww = wp[k4];
            vv += ww.x * phi_sm[4 * k4 + 0] + ww.y * phi_sm[4 * k4 + 1]
                + ww.z * phi_sm[4 * k4 + 2] + ww.w * phi_sm[4 * k4 + 3];
        }
        g_V[(size_t)bh * D_ + e] = vv;
    }
}

// ---------------- fused: energy + exp + context partials --------------------
// grid (NC, B), block 256, 2 CTAs/SM, 3-stage pipeline.
// smem float layout (~104 KB):
//   [0)      tiles   : 3 * ST*D = 24576
//   [24576)  pall    : UC*H     = 512    ([uu][h])
//   [25088)  p2      : ST*H*2   = 128    (u64 (p,p) per (r,h))
//   [25216)  lb_sm   : UC*H     = 512
//   [25728)  prevs   : UC+30    = 158
//   [25886)  keffs   : 124
//   [26010)  mbar    : 3 u64 (+pad)
#define SMEM_FUSED_FLOATS 26020
#define SMEM_FUSED_BYTES (SMEM_FUSED_FLOATS * 4)

__global__ void __launch_bounds__(256, 2)
fused_kernel(const float* __restrict__ enc,
             const float* __restrict__ prev)
{
    extern __shared__ float smem[];
    float* pall  = smem + NSTAGE * ST * D_;            // 24576
    unsigned long long* p2 =
        reinterpret_cast<unsigned long long*>(smem + 25088);
    float* lb_sm = smem + 25216;
    float* prevs = smem + 25728;
    float* keffs = smem + 25886;
    uint32_t barb = (smem_u32(smem + 26010) + 7) & ~7u;

    int tid  = threadIdx.x;
    int warp = tid >> 5, lane = tid & 31;
    int b  = blockIdx.y;
    int u0 = blockIdx.x * UC;
    const float* enc_base = enc + ((size_t)b * U_ + u0) * D_;

    if (tid == 0) {
        mbar_init(barb + 0, 1);
        mbar_init(barb + 8, 1);
        mbar_init(barb + 16, 1);
        fence_proxy_async_sc();
    }
    __syncthreads();

    if (tid == 0) {
        #pragma unroll
        for (int s = 0; s < NSTAGE; s++) {
            mbar_expect_tx(barb + 8 * s, TILE_BYTES);
            bulk_g2s(smem_u32(smem + s * ST * D_),
                     enc_base + s * ST * D_, TILE_BYTES, barb + 8 * s);
        }
    }

    // stage prev halo + keff while copies fly
    for (int i = tid; i < UC + 30; i += 256) {
        int gu = u0 + i - 15;
        prevs[i] = (gu >= 0 && gu < U_) ? prev[(size_t)b * U_ + gu] : 0.f;
    }
    if (tid < CK_ * H_) keffs[tid] = g_KEFF[tid];
    __syncthreads();

    // precompute location bias for all (uu, h) of this chunk
    #pragma unroll
    for (int j = 0; j < 2; j++) {
        int idx = tid + 256 * j;
        int uu = idx >> 2, h = idx & 3;
        float lb = 0.f;
        #pragma unroll
        for (int k = 0; k < CK_; k++)
            lb += prevs[uu + k] * keffs[k * H_ + h];
        lb_sm[idx] = lb;
    }

    // warp-pair head split: warp = pair*2 + j; heads {2j, 2j+1}
    int pairid = warp >> 1, j = warp & 1;
    ulonglong2 vr[2][4];
    #pragma unroll
    for (int g = 0; g < 2; g++) {
        const ulonglong2* vp = reinterpret_cast<const ulonglong2*>(
            g_V + (size_t)(b * H_ + 2 * j + g) * D_);
        #pragma unroll
        for (int i = 0; i < 4; i++) vr[g][i] = vp[lane + 32 * i];
    }

    unsigned long long ctx2[H_] = {0ull, 0ull, 0ull, 0ull};

    __syncthreads();  // lb_sm ready

    for (int s = 0; s < NSUB; s++) {
        int slot = s % NSTAGE;
        mbar_wait(barb + 8 * slot, (s / NSTAGE) & 1);
        const float* tile = smem + slot * ST * D_;

        // ---- energy + exp: warp handles rows pairid + 4t ----
        #pragma unroll
        for (int t = 0; t < 4; t++) {
            int r = pairid + 4 * t;
            const ulonglong2* row =
                reinterpret_cast<const ulonglong2*>(tile + r * D_);
            unsigned long long a2h[2] = {0ull, 0ull};
            #pragma unroll
            for (int i = 0; i < 4; i++) {
                ulonglong2 x = row[lane + 32 * i];
                fma2(a2h[0], x.x, vr[0][i].x);
                fma2(a2h[0], x.y, vr[0][i].y);
                fma2(a2h[1], x.x, vr[1][i].x);
                fma2(a2h[1], x.y, vr[1][i].y);
            }
            float2 f0 = unpack2(a2h[0]), f1 = unpack2(a2h[1]);
            float a0 = f0.x + f0.y, a1 = f1.x + f1.y;
            #pragma unroll
            for (int off = 16; off; off >>= 1) {
                a0 += __shfl_xor_sync(0xffffffffu, a0, off);
                a1 += __shfl_xor_sync(0xffffffffu, a1, off);
            }
            if (lane == 0) {
                int uu = s * ST + r;
                float2 lb = *reinterpret_cast<const float2*>(
                    lb_sm + uu * H_ + 2 * j);
                float p0 = __expf(a0 + lb.x);
                float p1 = __expf(a1 + lb.y);
                *reinterpret_cast<float2*>(pall + uu * H_ + 2 * j) =
                    make_float2(p0, p1);
                ulonglong2 pp;
                pp.x = pack2(p0, p0);
                pp.y = pack2(p1, p1);
                *reinterpret_cast<ulonglong2*>(p2 + r * H_ + 2 * j) = pp;
            }
        }
        __syncthreads();

        // ---- context accumulation (thread owns cols 2tid, 2tid+1) ----
        {
            const unsigned long long* tp =
                reinterpret_cast<const unsigned long long*>(tile) + tid;
            #pragma unroll 4
            for (int r = 0; r < ST; r++) {
                const ulonglong2* q =
                    reinterpret_cast<const ulonglong2*>(p2 + r * H_);
                ulonglong2 q01 = q[0], q23 = q[1];
                unsigned long long x = tp[r * (D_ / 2)];
                fma2(ctx2[0], x, q01.x);
                fma2(ctx2[1], x, q01.y);
                fma2(ctx2[2], x, q23.x);
                fma2(ctx2[3], x, q23.y);
            }
        }
        __syncthreads();

        // ---- prefetch subtile s+NSTAGE into freed slot ----
        if (tid == 0 && s + NSTAGE < NSUB) {
            mbar_expect_tx(barb + 8 * slot, TILE_BYTES);
            bulk_g2s(smem_u32(smem + slot * ST * D_),
                     enc_base + (s + NSTAGE) * ST * D_, TILE_BYTES, barb + 8 * slot);
        }
    }

    // ---- per-chunk sum of p ----
    size_t chunk = (size_t)b * NC + blockIdx.x;
    if (warp < H_) {
        float sp = pall[lane * H_ + warp] + pall[(lane + 32) * H_ + warp]
                 + pall[(lane + 64) * H_ + warp] + pall[(lane + 96) * H_ + warp];
        #pragma unroll
        for (int off = 16; off; off >>= 1)
            sp += __shfl_xor_sync(0xffffffffu, sp, off);
        if (lane == 0) g_SP[chunk * H_ + warp] = sp;
    }

    // ---- write ctx partials + raw p ----
    #pragma unroll
    for (int h = 0; h < H_; h++) {
        float2 f = unpack2(ctx2[h]);
        *reinterpret_cast<float2*>(
            g_CTXP + (chunk * H_ + h) * D_ + 2 * tid) = f;
    }
    #pragma unroll
    for (int jj = 0; jj < 2; jj++) {
        int idx = tid + 256 * jj;
        g_P[((size_t)b * U_ + u0) * H_ + idx] = pall[idx];
    }
}

// ---------------- combine partials per (b,h) --------------------------------
// grid (H, B), block 512; thread owns 1 column, 32 independent loads
__global__ void combine_kernel()
{
    int h = blockIdx.x, b = blockIdx.y;
    int tid = threadIdx.x;
    __shared__ float S_sm;

    if (tid < 32) {
        float sc = g_SP[((size_t)b * NC + tid) * H_ + h];
        #pragma unroll
        for (int off = 16; off; off >>= 1)
            sc += __shfl_xor_sync(0xffffffffu, sc, off);
        if (tid == 0) {
            S_sm = sc;
            g_S[b * H_ + h] = sc;
        }
    }
    __syncthreads();
    float invS = 1.f / S_sm;

    const float* base = g_CTXP + ((size_t)b * NC * H_ + h) * D_ + tid;
    float a = 0.f;
    #pragma unroll 8
    for (int c = 0; c < NC; c++)
        a += base[(size_t)c * H_ * D_];
    g_CTX[(size_t)(b * H_ + h) * D_ + tid] = a * invS;
}

// ---------------- attention weights (mean over heads) -----------------------
// grid (4, B), block 256; g_P is [b][u][h]
__global__ void aw_kernel(float* __restrict__ out)
{
    int z = blockIdx.x, b = blockIdx.y;
    float i0 = 0.25f / g_S[b * H_ + 0];
    float i1 = 0.25f / g_S[b * H_ + 1];
    float i2 = 0.25f / g_S[b * H_ + 2];
    float i3 = 0.25f / g_S[b * H_ + 3];
    const float4* p = reinterpret_cast<const float4*>(
        g_P + ((size_t)b * U_ + z * 1024) * H_);
    float* o = out + (size_t)B_ * AU_ + (size_t)b * U_ + z * 1024;
    for (int u = threadIdx.x; u < 1024; u += 256) {
        float4 v = p[u];
        o[u] = v.x * i0 + v.y * i1 + v.z * i2 + v.w * i3;
    }
}

// ---------------- out GEMM partials ------------------------------------------
__global__ void outp_kernel(const float* __restrict__ Wout)
{
    extern __shared__ float c_sm[];   // [b][i] : 32 x 512
    int cg = blockIdx.x, s = blockIdx.y;
    int tid = threadIdx.x;
    int col = cg * 32 + (tid & 31);
    int bg  = tid >> 5;

    for (int k = tid; k < 32 * 512; k += 256) {
        int bb = k >> 9, i = k & 511;
        c_sm[k] = g_CTX[(size_t)bb * (H_ * D_) + s * 512 + i];
    }
    __syncthreads();

    float acc0 = 0.f, acc1 = 0.f, acc2 = 0.f, acc3 = 0.f;
    const float* wp = Wout + (size_t)s * 512 * AU_ + col;
    const float* c0 = c_sm + (4 * bg + 0) * 512;
    const float* c1 = c_sm + (4 * bg + 1) * 512;
    const float* c2 = c_sm + (4 * bg + 2) * 512;
    const float* c3 = c_sm + (4 * bg + 3) * 512;
    #pragma unroll 8
    for (int i = 0; i < 512; i++) {
        float w = wp[(size_t)i * AU_];
        acc0 += c0[i] * w;
        acc1 += c1[i] * w;
        acc2 += c2[i] * w;
        acc3 += c3[i] * w;
    }
    float* op = g_OUTP + (size_t)s * B_ * AU_ + col;
    op[(4 * bg + 0) * AU_] = acc0;
    op[(4 * bg + 1) * AU_] = acc1;
    op[(4 * bg + 2) * AU_] = acc2;
    op[(4 * bg + 3) * AU_] = acc3;
}

// ---------------- out final: grid B, block 512 ------------------------------
__global__ void outf_kernel(const float* __restrict__ bout,
                            float* __restrict__ out)
{
    int b = blockIdx.x, t = threadIdx.x;
    float v = bout[t]
            + g_OUTP[(0 * B_ + b) * AU_ + t] + g_OUTP[(1 * B_ + b) * AU_ + t]
            + g_OUTP[(2 * B_ + b) * AU_ + t] + g_OUTP[(3 * B_ + b) * AU_ + t];
    out[(size_t)b * AU_ + t] = v;
}

// ---------------------------------------------------------------------------
extern "C" void kernel_launch(void* const* d_in, const int* in_sizes, int n_in,
                              void* d_out, int out_size)
{
    const float* dec   = (const float*)d_in[0];
    const float* enc   = (const float*)d_in[1];
    const float* prev  = (const float*)d_in[2];
    const float* Wphi  = (const float*)d_in[3];
    const float* bphi  = (const float*)d_in[4];
    const float* Wpsi  = (const float*)d_in[5];
    // d_in[6] = bpsi: constant along u per (b,h) -> softmax-invariant, unused
    const float* ck    = (const float*)d_in[7];
    const float* Wloc  = (const float*)d_in[8];
    const float* Wout  = (const float*)d_in[9];
    const float* bout  = (const float*)d_in[10];
    float* out = (float*)d_out;

    cudaFuncSetAttribute(fused_kernel,
                         cudaFuncAttributeMaxDynamicSharedMemorySize,
                         SMEM_FUSED_BYTES);
    cudaFuncSetAttribute(outp_kernel,
                         cudaFuncAttributeMaxDynamicSharedMemorySize,
                         32 * 512 * 4);

    keff_kernel<<<1, 128>>>(ck, Wloc);
    phiv_kernel<<<B_ * H_, 256>>>(dec, Wphi, bphi, Wpsi);
    fused_kernel<<<dim3(NC, B_), 256, SMEM_FUSED_BYTES>>>(enc, prev);
    combine_kernel<<<dim3(H_, B_), 512>>>();
    aw_kernel<<<dim3(4, B_), 256>>>(out);
    outp_kernel<<<dim3(16, 4), 256, 32 * 512 * 4>>>(Wout);
    outf_kernel<<<B_, 512>>>(bout, out);
}